// round 1
// baseline (speedup 1.0000x reference)
#include <cuda_runtime.h>
#include <cuda_bf16.h>
#include <math.h>

// Problem shape constants
#define BATCH   8
#define NN      64        // num nodes
#define KTOT    65536     // feature length = 64*32*32
#define SPLITS  64        // split-K factor
#define KCH     (KTOT / SPLITS)   // 1024 per CTA
#define ITERS   10

// Scratch: partial/accumulated Gram matrices [B][N][N]
__device__ float g_gram[BATCH * NN * NN];

// ---------------------------------------------------------------------------
// Kernel 0: zero the Gram scratch
// ---------------------------------------------------------------------------
__global__ void zero_gram_kernel() {
    int idx = blockIdx.x * blockDim.x + threadIdx.x;
    if (idx < BATCH * NN * NN) g_gram[idx] = 0.0f;
}

// ---------------------------------------------------------------------------
// Kernel 1: split-K Gram matrix, fp32 SIMT.
// grid = (SPLITS, BATCH), block = 256 threads.
// Each CTA: 64x64 partial Gram over a 1024-wide K chunk.
// Thread (tx,ty) in a 16x16 layout owns a 4x4 output micro-tile.
// Shared tile stored transposed As[k][row] (pad 65 -> conflict-free stores).
// ---------------------------------------------------------------------------
__global__ void __launch_bounds__(256, 4) gram_kernel(const float* __restrict__ feats) {
    __shared__ float As[64][65];

    const int b   = blockIdx.y;
    const int s   = blockIdx.x;
    const int tid = threadIdx.x;
    const int tx  = tid & 15;
    const int ty  = tid >> 4;
    const int r0  = ty * 4;
    const int c0  = tx * 4;

    float acc[4][4];
#pragma unroll
    for (int i = 0; i < 4; ++i)
#pragma unroll
        for (int j = 0; j < 4; ++j) acc[i][j] = 0.0f;

    const float* base = feats + (size_t)b * NN * KTOT + (size_t)s * KCH;

    for (int kt = 0; kt < KCH; kt += 64) {
        // Load 64 rows x 64 k-values, transposed into As[k][row].
        // Consecutive tids read consecutive k within a row -> coalesced 256B/row.
#pragma unroll
        for (int t = tid; t < 4096; t += 256) {
            const int row = t >> 6;
            const int k   = t & 63;
            As[k][row] = base[(size_t)row * KTOT + kt + k];
        }
        __syncthreads();

#pragma unroll 8
        for (int k = 0; k < 64; ++k) {
            const float a0 = As[k][r0 + 0];
            const float a1 = As[k][r0 + 1];
            const float a2 = As[k][r0 + 2];
            const float a3 = As[k][r0 + 3];
            const float b0 = As[k][c0 + 0];
            const float b1 = As[k][c0 + 1];
            const float b2 = As[k][c0 + 2];
            const float b3 = As[k][c0 + 3];
            acc[0][0] += a0 * b0; acc[0][1] += a0 * b1; acc[0][2] += a0 * b2; acc[0][3] += a0 * b3;
            acc[1][0] += a1 * b0; acc[1][1] += a1 * b1; acc[1][2] += a1 * b2; acc[1][3] += a1 * b3;
            acc[2][0] += a2 * b0; acc[2][1] += a2 * b1; acc[2][2] += a2 * b2; acc[2][3] += a2 * b3;
            acc[3][0] += a3 * b0; acc[3][1] += a3 * b1; acc[3][2] += a3 * b2; acc[3][3] += a3 * b3;
        }
        __syncthreads();
    }

    // Accumulate partial Gram into global scratch.
    float* gb = g_gram + b * NN * NN;
#pragma unroll
    for (int i = 0; i < 4; ++i)
#pragma unroll
        for (int j = 0; j < 4; ++j)
            atomicAdd(&gb[(r0 + i) * NN + (c0 + j)], acc[i][j]);
}

// ---------------------------------------------------------------------------
// Kernel 2: CRF iterations + output.
// grid = BATCH, block = 64 threads (thread i owns row i).
// State reduction: l[b,i,j] = logits[b,j] + e[i], so only e (len 64) evolves:
//   e'[i] = sum_j (2*sigmoid(logits[i] + e[j]) - 1) * pp[i,j],  e0 = 0
//   out[b,j] = logits[b,j] + mean_i(e[i])
// ---------------------------------------------------------------------------
__global__ void crf_kernel(const float* __restrict__ logits,
                           const float* __restrict__ W,
                           float* __restrict__ out) {
    const int b = blockIdx.x;
    const int i = threadIdx.x;   // 0..63

    __shared__ float pp[64][65];
    __shared__ float e[64];
    __shared__ float nrm[64];
    __shared__ float lg[64];
    __shared__ float red[64];

    const float* gb = g_gram + b * NN * NN;

    nrm[i] = sqrtf(gb[i * NN + i]);
    lg[i]  = logits[b * NN + i];
    __syncthreads();

    const float ni = nrm[i];
#pragma unroll 4
    for (int j = 0; j < NN; ++j) {
        const float dot  = gb[i * NN + j];
        const float sim  = dot / (ni * nrm[j] + 1e-6f);
        const float wsym = 0.5f * (W[i * NN + j] + W[j * NN + i]);
        pp[i][j] = sim * wsym;
    }
    e[i] = 0.0f;
    __syncthreads();

    const float li = lg[i];
    for (int it = 0; it < ITERS; ++it) {
        float acc = 0.0f;
#pragma unroll 8
        for (int j = 0; j < NN; ++j) {
            const float p = 1.0f / (1.0f + expf(-(li + e[j])));
            acc += (2.0f * p - 1.0f) * pp[i][j];
        }
        __syncthreads();
        e[i] = acc;
        __syncthreads();
    }

    // mean over e
    red[i] = e[i];
    __syncthreads();
    for (int s = 32; s > 0; s >>= 1) {
        if (i < s) red[i] += red[i + s];
        __syncthreads();
    }
    const float meanE = red[0] * (1.0f / 64.0f);
    out[b * NN + i] = lg[i] + meanE;
}

// ---------------------------------------------------------------------------
// Launch
// ---------------------------------------------------------------------------
extern "C" void kernel_launch(void* const* d_in, const int* in_sizes, int n_in,
                              void* d_out, int out_size) {
    const float* a_inter = (const float*)d_in[0];  // [8,64,64,32,32]
    const float* logits  = (const float*)d_in[1];  // [8,64]
    const float* W       = (const float*)d_in[2];  // [1,64,64]
    float* out           = (float*)d_out;          // [8,64]

    zero_gram_kernel<<<(BATCH * NN * NN + 255) / 256, 256>>>();

    dim3 grid(SPLITS, BATCH);
    gram_kernel<<<grid, 256>>>(a_inter);

    crf_kernel<<<BATCH, 64>>>(logits, W, out);
}

// round 3
// speedup vs baseline: 1.9681x; 1.9681x over previous
#include <cuda_runtime.h>
#include <cuda_bf16.h>
#include <math.h>
#include <stdint.h>

#define BATCH   8
#define NN      64
#define KTOT    65536
#define SPLITS  64
#define KCH     (KTOT / SPLITS)   // 1024
#define TILE_K  32
#define NTILES  (KCH / TILE_K)    // 32
#define SSTRIDE 36                // smem row stride (floats): banks = 4*row + k -> conflict-free
#define ITERS   10

// Gram scratch [B][N][N], accumulated via atomics
__device__ float g_gram[BATCH * NN * NN];

// ---------------------------------------------------------------------------
// Kernel 0: zero the Gram scratch
// ---------------------------------------------------------------------------
__global__ void zero_gram_kernel() {
    int idx = blockIdx.x * blockDim.x + threadIdx.x;
    if (idx < BATCH * NN * NN) g_gram[idx] = 0.0f;
}

// ---------------------------------------------------------------------------
// Kernel 1: split-K Gram via warp-level tf32 mma.sync (m16n8k8).
// grid = (SPLITS, BATCH), block = 256 (8 warps, 4(M) x 2(N)).
// Each CTA: C[64,64] partial = A_chunk @ A_chunk^T over K=1024.
// Double-buffered smem tile As[64][32] (stride 36), shared by A and B roles.
// ---------------------------------------------------------------------------
__global__ void __launch_bounds__(256) gram_mma_kernel(const float* __restrict__ feats) {
    __shared__ uint32_t As[2][64 * SSTRIDE];

    const int tid   = threadIdx.x;
    const int wid   = tid >> 5;
    const int lane  = tid & 31;
    const int group = lane >> 2;     // 0..7
    const int tg    = lane & 3;      // 0..3
    const int wm    = wid >> 1;      // 0..3 -> C rows [wm*16, +16)
    const int wn    = wid & 1;       // 0..1 -> C cols [wn*32, +32)

    const int b = blockIdx.y;
    const int s = blockIdx.x;
    const float* base = feats + (size_t)b * NN * KTOT + (size_t)s * KCH;

    // gmem->reg fill assignment: 2 float4 chunks per thread
    const int c0row = tid >> 3,   c0c4 = tid & 7;          // chunk tid
    const int c1row = (tid + 256) >> 3, c1c4 = (tid + 256) & 7; // chunk tid+256

    float c[4][4];   // 4 n8-tiles x 4 accum regs
#pragma unroll
    for (int i = 0; i < 4; ++i)
#pragma unroll
        for (int j = 0; j < 4; ++j) c[i][j] = 0.0f;

    // prefetch tile 0
    float4 p0 = *reinterpret_cast<const float4*>(base + (size_t)c0row * KTOT + c0c4 * 4);
    float4 p1 = *reinterpret_cast<const float4*>(base + (size_t)c1row * KTOT + c1c4 * 4);

    for (int t = 0; t < NTILES; ++t) {
        const int buf = t & 1;
        // store prefetched tile t into smem (with fp32->tf32 RN convert)
        {
            uint4 w0, w1;
            asm("cvt.rna.tf32.f32 %0, %1;" : "=r"(w0.x) : "f"(p0.x));
            asm("cvt.rna.tf32.f32 %0, %1;" : "=r"(w0.y) : "f"(p0.y));
            asm("cvt.rna.tf32.f32 %0, %1;" : "=r"(w0.z) : "f"(p0.z));
            asm("cvt.rna.tf32.f32 %0, %1;" : "=r"(w0.w) : "f"(p0.w));
            asm("cvt.rna.tf32.f32 %0, %1;" : "=r"(w1.x) : "f"(p1.x));
            asm("cvt.rna.tf32.f32 %0, %1;" : "=r"(w1.y) : "f"(p1.y));
            asm("cvt.rna.tf32.f32 %0, %1;" : "=r"(w1.z) : "f"(p1.z));
            asm("cvt.rna.tf32.f32 %0, %1;" : "=r"(w1.w) : "f"(p1.w));
            *reinterpret_cast<uint4*>(&As[buf][c0row * SSTRIDE + c0c4 * 4]) = w0;
            *reinterpret_cast<uint4*>(&As[buf][c1row * SSTRIDE + c1c4 * 4]) = w1;
        }
        // issue prefetch for tile t+1 before consuming tile t
        if (t + 1 < NTILES) {
            const float* nxt = base + (t + 1) * TILE_K;
            p0 = *reinterpret_cast<const float4*>(nxt + (size_t)c0row * KTOT + c0c4 * 4);
            p1 = *reinterpret_cast<const float4*>(nxt + (size_t)c1row * KTOT + c1c4 * 4);
        }
        __syncthreads();

        const uint32_t* S = &As[buf][0];
#pragma unroll
        for (int kk = 0; kk < 4; ++kk) {        // 4 k-steps of 8
            const int k0 = kk * 8;
            const uint32_t a0 = S[(wm * 16 + group)     * SSTRIDE + k0 + tg];
            const uint32_t a1 = S[(wm * 16 + group + 8) * SSTRIDE + k0 + tg];
            const uint32_t a2 = S[(wm * 16 + group)     * SSTRIDE + k0 + tg + 4];
            const uint32_t a3 = S[(wm * 16 + group + 8) * SSTRIDE + k0 + tg + 4];
#pragma unroll
            for (int nt = 0; nt < 4; ++nt) {
                const int col = wn * 32 + nt * 8 + group;
                const uint32_t b0 = S[col * SSTRIDE + k0 + tg];
                const uint32_t b1 = S[col * SSTRIDE + k0 + tg + 4];
                asm volatile(
                    "mma.sync.aligned.m16n8k8.row.col.f32.tf32.tf32.f32 "
                    "{%0,%1,%2,%3}, {%4,%5,%6,%7}, {%8,%9}, {%0,%1,%2,%3};"
                    : "+f"(c[nt][0]), "+f"(c[nt][1]), "+f"(c[nt][2]), "+f"(c[nt][3])
                    : "r"(a0), "r"(a1), "r"(a2), "r"(a3), "r"(b0), "r"(b1));
            }
        }
        __syncthreads();
    }

    // epilogue: atomic-accumulate partial C into g_gram[b]
    float* gb = g_gram + (size_t)b * NN * NN;
    const int r0 = wm * 16 + group;
#pragma unroll
    for (int nt = 0; nt < 4; ++nt) {
        const int col = wn * 32 + nt * 8 + tg * 2;
        atomicAdd(&gb[(r0)     * NN + col    ], c[nt][0]);
        atomicAdd(&gb[(r0)     * NN + col + 1], c[nt][1]);
        atomicAdd(&gb[(r0 + 8) * NN + col    ], c[nt][2]);
        atomicAdd(&gb[(r0 + 8) * NN + col + 1], c[nt][3]);
    }
}

// ---------------------------------------------------------------------------
// Kernel 2: CRF iterations + output.
// State reduction: l[b,i,j] = logits[b,j] + e[i]; only e (len 64) evolves:
//   e'[i] = sum_j (2*sigmoid(logits[i] + e[j]) - 1) * pp[i,j],  e0 = 0
//   out[b,j] = logits[b,j] + mean_i(e[i])
// ---------------------------------------------------------------------------
__global__ void crf_kernel(const float* __restrict__ logits,
                           const float* __restrict__ W,
                           float* __restrict__ out) {
    const int b = blockIdx.x;
    const int i = threadIdx.x;   // 0..63

    __shared__ float pp[64][65];
    __shared__ float e[64];
    __shared__ float nrm[64];
    __shared__ float lg[64];
    __shared__ float red[64];

    const float* gb = g_gram + b * NN * NN;

    nrm[i] = sqrtf(gb[i * NN + i]);
    lg[i]  = logits[b * NN + i];
    __syncthreads();

    const float ni = nrm[i];
#pragma unroll 4
    for (int j = 0; j < NN; ++j) {
        const float dot  = gb[i * NN + j];
        const float sim  = dot / (ni * nrm[j] + 1e-6f);
        const float wsym = 0.5f * (W[i * NN + j] + W[j * NN + i]);
        pp[i][j] = sim * wsym;
    }
    e[i] = 0.0f;
    __syncthreads();

    const float li = lg[i];
    for (int it = 0; it < ITERS; ++it) {
        float acc = 0.0f;
#pragma unroll 8
        for (int j = 0; j < NN; ++j) {
            const float p = 1.0f / (1.0f + expf(-(li + e[j])));
            acc += (2.0f * p - 1.0f) * pp[i][j];
        }
        __syncthreads();
        e[i] = acc;
        __syncthreads();
    }

    red[i] = e[i];
    __syncthreads();
    for (int s = 32; s > 0; s >>= 1) {
        if (i < s) red[i] += red[i + s];
        __syncthreads();
    }
    const float meanE = red[0] * (1.0f / 64.0f);
    out[b * NN + i] = lg[i] + meanE;
}

// ---------------------------------------------------------------------------
// Launch
// ---------------------------------------------------------------------------
extern "C" void kernel_launch(void* const* d_in, const int* in_sizes, int n_in,
                              void* d_out, int out_size) {
    const float* a_inter = (const float*)d_in[0];  // [8,64,64,32,32]
    const float* logits  = (const float*)d_in[1];  // [8,64]
    const float* W       = (const float*)d_in[2];  // [1,64,64]
    float* out           = (float*)d_out;          // [8,64]

    zero_gram_kernel<<<(BATCH * NN * NN + 255) / 256, 256>>>();

    dim3 grid(SPLITS, BATCH);
    gram_mma_kernel<<<grid, 256>>>(a_inter);

    crf_kernel<<<BATCH, 64>>>(logits, W, out);
}

// round 4
// speedup vs baseline: 2.2415x; 1.1389x over previous
#include <cuda_runtime.h>
#include <cuda_fp16.h>
#include <cuda_bf16.h>
#include <math.h>
#include <stdint.h>

#define BATCH   8
#define NN      64
#define KTOT    65536
#define SPLITS  64
#define KCH     (KTOT / SPLITS)   // 1024
#define TILE_K  32
#define NTILES  (KCH / TILE_K)    // 32
#define HSTRIDE 40                // smem row stride in halves (80B): 16B-aligned rows, conflict-free ldmatrix
#define ITERS   10

// Gram scratch [B][N][N], accumulated via atomics
__device__ float g_gram[BATCH * NN * NN];

// ---------------------------------------------------------------------------
// Kernel 0: zero the Gram scratch
// ---------------------------------------------------------------------------
__global__ void zero_gram_kernel() {
    int idx = blockIdx.x * blockDim.x + threadIdx.x;
    if (idx < BATCH * NN * NN) g_gram[idx] = 0.0f;
}

__device__ __forceinline__ uint32_t smem_u32(const void* p) {
    return (uint32_t)__cvta_generic_to_shared(p);
}

// ---------------------------------------------------------------------------
// Kernel 1: split-K Gram via fp16 mma.sync m16n8k16 + ldmatrix.
// grid = (SPLITS, BATCH), block = 256 (8 warps: 4(M) x 2(N)).
// Each CTA: C[64,64] partial = A_chunk @ A_chunk^T over K=1024.
// Double-buffered smem tile [64 rows x 32 halves], row stride 40 halves.
// One __syncthreads per tile: mma reads buf[t&1] while stores fill buf[(t+1)&1].
// ---------------------------------------------------------------------------
__global__ void __launch_bounds__(256) gram_mma_kernel(const float* __restrict__ feats) {
    __shared__ __align__(16) __half As[2][64 * HSTRIDE];

    const int tid  = threadIdx.x;
    const int wid  = tid >> 5;
    const int lane = tid & 31;
    const int tg   = lane & 3;       // 0..3
    const int wm   = wid >> 1;       // 0..3 -> C rows [wm*16, +16)
    const int wn   = wid & 1;        // 0..1 -> C cols [wn*32, +32)

    const int b = blockIdx.y;
    const int s = blockIdx.x;
    const float* base = feats + (size_t)b * NN * KTOT + (size_t)s * KCH;

    // fill assignment: 2 float4 chunks per thread (rows 0..31 then 32..63)
    const int c0row = tid >> 3,           c0c4 = tid & 7;
    const int c1row = (tid + 256) >> 3,   c1c4 = (tid + 256) & 7;

    // ldmatrix source addresses (constant per thread across tiles, modulo buf + kk)
    // A: lanes 0-7 -> rows r0..r0+7 @ k0 ; 8-15 -> rows+8 @ k0 ; 16-23 -> rows @ k8 ; 24-31 -> rows+8 @ k8
    const int a_row  = wm * 16 + (lane & 7) + ((lane >> 3) & 1) * 8;
    const int a_koff = (lane >> 4) * 8;
    // B (two x4 loads): lanes 0-7 -> cols c..c+7 @ k0 ; 8-15 same cols @ k8 ; 16-23 -> cols+8 @ k0 ; 24-31 -> cols+8 @ k8
    const int b_col  = wn * 32 + (lane & 7) + ((lane >> 4) & 1) * 8;
    const int b_koff = ((lane >> 3) & 1) * 8;

    float c[4][4];
#pragma unroll
    for (int i = 0; i < 4; ++i)
#pragma unroll
        for (int j = 0; j < 4; ++j) c[i][j] = 0.0f;

    // helper lambda-ish macro: convert float4 -> 2x half2 and store 8B
#define STORE_H4(buf, row, c4, v)                                              \
    do {                                                                       \
        __half2 h0 = __float22half2_rn(make_float2((v).x, (v).y));             \
        __half2 h1 = __float22half2_rn(make_float2((v).z, (v).w));             \
        *reinterpret_cast<__half2*>(&As[buf][(row) * HSTRIDE + (c4) * 4])     = h0; \
        *reinterpret_cast<__half2*>(&As[buf][(row) * HSTRIDE + (c4) * 4 + 2]) = h1; \
    } while (0)

    // prologue: load tile 0, store into buf 0
    {
        float4 p0 = *reinterpret_cast<const float4*>(base + (size_t)c0row * KTOT + c0c4 * 4);
        float4 p1 = *reinterpret_cast<const float4*>(base + (size_t)c1row * KTOT + c1c4 * 4);
        STORE_H4(0, c0row, c0c4, p0);
        STORE_H4(0, c1row, c1c4, p1);
    }

    for (int t = 0; t < NTILES; ++t) {
        __syncthreads();   // buf[t&1] filled & all warps done with mma of t-1 (protects buf[(t+1)&1])
        const int buf = t & 1;

        // prefetch tile t+1 (registers)
        float4 p0, p1;
        if (t + 1 < NTILES) {
            const float* nxt = base + (t + 1) * TILE_K;
            p0 = *reinterpret_cast<const float4*>(nxt + (size_t)c0row * KTOT + c0c4 * 4);
            p1 = *reinterpret_cast<const float4*>(nxt + (size_t)c1row * KTOT + c1c4 * 4);
        }

        // mainloop: 2 k-steps of 16
        const __half* S = &As[buf][0];
#pragma unroll
        for (int kk = 0; kk < 2; ++kk) {
            const int k0 = kk * 16;
            uint32_t a0, a1, a2, a3;
            {
                uint32_t addr = smem_u32(S + a_row * HSTRIDE + k0 + a_koff);
                asm volatile("ldmatrix.sync.aligned.m8n8.x4.shared.b16 {%0,%1,%2,%3}, [%4];"
                             : "=r"(a0), "=r"(a1), "=r"(a2), "=r"(a3) : "r"(addr));
            }
            uint32_t b01[2], b23[2], b45[2], b67[2];
            {
                uint32_t addr = smem_u32(S + b_col * HSTRIDE + k0 + b_koff);
                asm volatile("ldmatrix.sync.aligned.m8n8.x4.shared.b16 {%0,%1,%2,%3}, [%4];"
                             : "=r"(b01[0]), "=r"(b01[1]), "=r"(b23[0]), "=r"(b23[1]) : "r"(addr));
            }
            {
                uint32_t addr = smem_u32(S + (b_col + 16) * HSTRIDE + k0 + b_koff);
                asm volatile("ldmatrix.sync.aligned.m8n8.x4.shared.b16 {%0,%1,%2,%3}, [%4];"
                             : "=r"(b45[0]), "=r"(b45[1]), "=r"(b67[0]), "=r"(b67[1]) : "r"(addr));
            }
#define MMA16(acc, bb)                                                          \
    asm volatile("mma.sync.aligned.m16n8k16.row.col.f32.f16.f16.f32 "          \
                 "{%0,%1,%2,%3}, {%4,%5,%6,%7}, {%8,%9}, {%0,%1,%2,%3};"       \
                 : "+f"(acc[0]), "+f"(acc[1]), "+f"(acc[2]), "+f"(acc[3])      \
                 : "r"(a0), "r"(a1), "r"(a2), "r"(a3), "r"(bb[0]), "r"(bb[1]))
            MMA16(c[0], b01);
            MMA16(c[1], b23);
            MMA16(c[2], b45);
            MMA16(c[3], b67);
#undef MMA16
        }

        // store prefetched tile t+1 into the other buffer
        if (t + 1 < NTILES) {
            const int nbuf = buf ^ 1;
            STORE_H4(nbuf, c0row, c0c4, p0);
            STORE_H4(nbuf, c1row, c1c4, p1);
        }
    }
#undef STORE_H4

    // epilogue: atomic-accumulate partial C into g_gram[b]
    float* gb = g_gram + (size_t)b * NN * NN;
    const int r0 = wm * 16 + (lane >> 2);
#pragma unroll
    for (int nt = 0; nt < 4; ++nt) {
        const int col = wn * 32 + nt * 8 + tg * 2;
        atomicAdd(&gb[(r0)     * NN + col    ], c[nt][0]);
        atomicAdd(&gb[(r0)     * NN + col + 1], c[nt][1]);
        atomicAdd(&gb[(r0 + 8) * NN + col    ], c[nt][2]);
        atomicAdd(&gb[(r0 + 8) * NN + col + 1], c[nt][3]);
    }
}

// ---------------------------------------------------------------------------
// Kernel 2: CRF iterations + output.
// State reduction: l[b,i,j] = logits[b,j] + e[i]; only e (len 64) evolves:
//   e'[i] = sum_j (2*sigmoid(logits[i] + e[j]) - 1) * pp[i,j],  e0 = 0
//   out[b,j] = logits[b,j] + mean_i(e[i])
// ---------------------------------------------------------------------------
__global__ void crf_kernel(const float* __restrict__ logits,
                           const float* __restrict__ W,
                           float* __restrict__ out) {
    const int b = blockIdx.x;
    const int i = threadIdx.x;   // 0..63

    __shared__ float pp[64][65];
    __shared__ float e[64];
    __shared__ float nrm[64];
    __shared__ float lg[64];
    __shared__ float red[64];

    const float* gb = g_gram + b * NN * NN;

    nrm[i] = sqrtf(gb[i * NN + i]);
    lg[i]  = logits[b * NN + i];
    __syncthreads();

    const float ni = nrm[i];
#pragma unroll 4
    for (int j = 0; j < NN; ++j) {
        const float dot  = gb[i * NN + j];
        const float sim  = dot / (ni * nrm[j] + 1e-6f);
        const float wsym = 0.5f * (W[i * NN + j] + W[j * NN + i]);
        pp[i][j] = sim * wsym;
    }
    e[i] = 0.0f;
    __syncthreads();

    const float li = lg[i];
    for (int it = 0; it < ITERS; ++it) {
        float acc = 0.0f;
#pragma unroll 8
        for (int j = 0; j < NN; ++j) {
            const float p = 1.0f / (1.0f + expf(-(li + e[j])));
            acc += (2.0f * p - 1.0f) * pp[i][j];
        }
        __syncthreads();
        e[i] = acc;
        __syncthreads();
    }

    red[i] = e[i];
    __syncthreads();
    for (int s = 32; s > 0; s >>= 1) {
        if (i < s) red[i] += red[i + s];
        __syncthreads();
    }
    const float meanE = red[0] * (1.0f / 64.0f);
    out[b * NN + i] = lg[i] + meanE;
}

// ---------------------------------------------------------------------------
// Launch
// ---------------------------------------------------------------------------
extern "C" void kernel_launch(void* const* d_in, const int* in_sizes, int n_in,
                              void* d_out, int out_size) {
    const float* a_inter = (const float*)d_in[0];  // [8,64,64,32,32]
    const float* logits  = (const float*)d_in[1];  // [8,64]
    const float* W       = (const float*)d_in[2];  // [1,64,64]
    float* out           = (float*)d_out;          // [8,64]

    zero_gram_kernel<<<(BATCH * NN * NN + 255) / 256, 256>>>();

    dim3 grid(SPLITS, BATCH);
    gram_mma_kernel<<<grid, 256>>>(a_inter);

    crf_kernel<<<BATCH, 64>>>(logits, W, out);
}